// round 8
// baseline (speedup 1.0000x reference)
#include <cuda_runtime.h>
#include <cstdint>

// ---------------- configuration ----------------
#define S           256         // tile-table stride (num_tile=16 -> nt2=256)
#define MAX_ROWS    16384       // N up to 4.19M at 256 pts/row
#define MAX_CHUNKS  256
#define PPW         256         // points per warp (one hist "row")
#define WPB         8           // warps per block
#define CHUNK       64          // rows per scan chunk
#define GTHREADS    256         // gather block size

// ---------------- static scratch (no runtime allocation) ----------------
__device__ int      g_hist [MAX_ROWS * S];    // per-row hist -> final global base table
__device__ int      g_chunk[MAX_CHUNKS * S];  // per-chunk totals -> exclusive prefixes
__device__ int      g_offsets[S];             // global tile offsets
__device__ unsigned g_packed[MAX_ROWS * PPW]; // per-point (rank<<16 | key)
__device__ int      g_perm  [MAX_ROWS * PPW]; // perm[r] = source index

// ---------------- helpers ----------------
__device__ __forceinline__ int tile_of(float v, float ts, int nt) {
    int t = (int)floorf(v / ts);
    t = t < 0 ? 0 : t;
    t = t > nt - 1 ? nt - 1 : t;
    return t;
}

// ---------------- pass 1: fused histogram + stable within-row rank ----------------
__global__ void k_hist(const float2* __restrict__ pos, const int* __restrict__ p_nt,
                       int N, int ROWS) {
    __shared__ int sh[WPB * S];   // 8 KB
    const int nt  = *p_nt;
    const int nt2 = nt * nt;
    const float ts = 1024.0f / (float)nt;

    const int w    = threadIdx.x >> 5;
    const int lane = threadIdx.x & 31;
    const int row  = blockIdx.x * WPB + w;

    for (int t = lane; t < nt2; t += 32) sh[w * S + t] = 0;
    __syncwarp();

    if (row >= ROWS) return;

    const int base = row * PPW;
    const unsigned lt_mask = (1u << lane) - 1u;

#pragma unroll
    for (int i = 0; i < PPW / 32; i++) {
        int idx = base + i * 32 + lane;
        bool valid = idx < N;
        int key = 0x7FFFFFFF;
        if (valid) {
            float2 p = pos[idx];
            int tx = tile_of(p.x, ts, nt);
            int ty = tile_of(p.y, ts, nt);
            key = ty * nt + tx;
        }

        unsigned m  = __match_any_sync(0xFFFFFFFFu, key);
        int leader  = __ffs(m) - 1;
        int cnt     = __popc(m);
        int rank_lt = __popc(m & lt_mask);

        int old = 0;
        if (lane == leader && valid) {
            old = sh[w * S + key];           // single writer per address
            sh[w * S + key] = old + cnt;
        }
        old = __shfl_sync(0xFFFFFFFFu, old, leader);

        if (valid)
            g_packed[idx] = (unsigned)key | ((unsigned)(old + rank_lt) << 16);
    }
    __syncwarp();
    for (int t = lane; t < nt2; t += 32)
        g_hist[(size_t)row * S + t] = sh[w * S + t];
}

// ---------------- pass 2a: per-tile scan over rows within each chunk ----------------
__global__ void k_scan_rows(const int* __restrict__ p_nt, int ROWS) {
    const int nt  = *p_nt;
    const int nt2 = nt * nt;
    const int c  = blockIdx.x;
    const int r0 = c * CHUNK;
    const int r1 = min(r0 + CHUNK, ROWS);

    for (int t = threadIdx.x; t < nt2; t += blockDim.x) {
        int run = 0;
        for (int r = r0; r < r1; r += 8) {
            int m = min(8, r1 - r);
            int v[8];
#pragma unroll
            for (int j = 0; j < 8; j++)
                if (j < m) v[j] = g_hist[(size_t)(r + j) * S + t];
#pragma unroll
            for (int j = 0; j < 8; j++)
                if (j < m) {
                    g_hist[(size_t)(r + j) * S + t] = run;
                    run += v[j];
                }
        }
        g_chunk[(size_t)c * S + t] = run;
    }
}

// ---------------- pass 2b: scan chunks per tile, then scan over tiles ----------------
__global__ void k_scan_tiles(const int* __restrict__ p_nt, int NCHUNKS,
                             float* __restrict__ out, int N) {
    __shared__ int s[1024];
    const int nt  = *p_nt;
    const int nt2 = nt * nt;
    const int t = threadIdx.x;

    int total = 0;
    if (t < nt2) {
        int run = 0;
        for (int c = 0; c < NCHUNKS; c += 8) {
            int m = min(8, NCHUNKS - c);
            int v[8];
#pragma unroll
            for (int j = 0; j < 8; j++)
                if (j < m) v[j] = g_chunk[(size_t)(c + j) * S + t];
#pragma unroll
            for (int j = 0; j < 8; j++)
                if (j < m) {
                    g_chunk[(size_t)(c + j) * S + t] = run;
                    run += v[j];
                }
        }
        total = run;
    }
    s[t] = total;
    __syncthreads();

    for (int off = 1; off < 1024; off <<= 1) {
        int v = (t >= off) ? s[t - off] : 0;
        __syncthreads();
        s[t] += v;
        __syncthreads();
    }
    int excl = s[t] - total;

    if (t < nt2) {
        g_offsets[t] = excl;
        size_t feat_sz = (size_t)7 * (size_t)N;
        out[feat_sz + t]       = (float)total;  // tile_counts
        out[feat_sz + nt2 + t] = (float)excl;   // tile_offsets
    }
}

// ---------------- pass 2c: fuse prefix layers into one final base table ----------------
// g_hist[row][t] += g_offsets[t] + g_chunk[row/CHUNK][t]   (pure throughput)
__global__ void k_fuse(const int* __restrict__ p_nt, int ROWS) {
    const int nt  = *p_nt;
    const int nt2 = nt * nt;
    const int row = blockIdx.x;
    const int t   = threadIdx.x;
    if (row >= ROWS || t >= nt2) return;
    g_hist[(size_t)row * S + t] += g_offsets[t] + g_chunk[(size_t)(row / CHUNK) * S + t];
}

// ---------------- pass 3a: smem-free permutation scatter (1 thread/point) ----------------
__global__ void k_perm(int N) {
    int idx = blockIdx.x * blockDim.x + threadIdx.x;
    if (idx >= N) return;
    unsigned pk = g_packed[idx];
    int key  = (int)(pk & 0xFFFFu);
    int rank = (int)(pk >> 16);
    int row  = idx / PPW;
    int dst  = g_hist[(size_t)row * S + key] + rank;
    g_perm[dst] = idx;
}

// ---------------- pass 3b: gather + compute + coalesced wide stores ----------------
__global__ void k_gather(const float2* __restrict__ pos,
                         const float4* __restrict__ cov,
                         const float*  __restrict__ opac,
                         const int*    __restrict__ p_nt,
                         int N,
                         float* __restrict__ out) {
    __shared__ float s[GTHREADS * 7];   // stride 7 -> conflict-free
    const int nt  = *p_nt;
    const int nt2 = nt * nt;

    const int tid = threadIdx.x;
    const int r0  = blockIdx.x * GTHREADS;
    const int r   = r0 + tid;

    float* __restrict__ out_order = out + (size_t)7 * (size_t)N + 2 * (size_t)nt2;

    if (r < N) {
        int idx = g_perm[r];
        float2 p  = __ldg(&pos[idx]);
        float4 cv = __ldg(&cov[idx]);
        float  op = __ldg(&opac[idx]);

        float a = cv.x, b = cv.y, c = cv.z, d = cv.w;
        float tr  = a + d;
        float det = a * d - b * c;
        float t1  = 0.5f * tr;
        float t2  = 0.5f * sqrtf(fmaxf(tr * tr - 4.0f * det, 0.0f));
        float rad = fmaxf(t1 - t2, t1 + t2);
        float inv_det = 1.0f / det;

        float* sf = s + tid * 7;
        sf[0] = p.x;  sf[1] = p.y;
        sf[2] =  d * inv_det;
        sf[3] = -b * inv_det;
        sf[4] =  a * inv_det;
        sf[5] = op;   sf[6] = rad;

        out_order[r] = (float)idx;
    }
    __syncthreads();

    int count = min(GTHREADS, N - r0);
    if (count == GTHREADS) {
        // full tile: 1792 floats = 448 float4, base aligned (r0 multiple of 256)
        float4* dst = (float4*)(out + (size_t)r0 * 7);
        const float4* src = (const float4*)s;
#pragma unroll
        for (int i = 0; i < 2; i++) {
            int j = tid + i * GTHREADS;
            if (j < (GTHREADS * 7) / 4) dst[j] = src[j];
        }
    } else if (count > 0) {
        float* dst = out + (size_t)r0 * 7;
        int nf = count * 7;
        for (int j = tid; j < nf; j += GTHREADS) dst[j] = s[j];
    }
}

// ---------------- launch ----------------
extern "C" void kernel_launch(void* const* d_in, const int* in_sizes, int n_in,
                              void* d_out, int out_size) {
    const float2* pos  = (const float2*)d_in[0];
    const float4* cov  = (const float4*)d_in[1];
    const float*  opac = (const float*) d_in[2];
    const int*    p_nt = (const int*)   d_in[3];
    float* out = (float*)d_out;

    const int N       = in_sizes[0] / 2;
    const int ROWS    = (N + PPW - 1) / PPW;
    const int NBLOCKS = (ROWS + WPB - 1) / WPB;
    const int NCHUNKS = (ROWS + CHUNK - 1) / CHUNK;
    const int GBLOCKS = (N + GTHREADS - 1) / GTHREADS;
    const int PBLOCKS = (N + 255) / 256;

    k_hist      <<<NBLOCKS, 256>>>(pos, p_nt, N, ROWS);
    k_scan_rows <<<NCHUNKS, 256>>>(p_nt, ROWS);
    k_scan_tiles<<<1, 1024>>>(p_nt, NCHUNKS, out, N);
    k_fuse      <<<ROWS, 256>>>(p_nt, ROWS);
    k_perm      <<<PBLOCKS, 256>>>(N);
    k_gather    <<<GBLOCKS, GTHREADS>>>(pos, cov, opac, p_nt, N, out);
}

// round 9
// speedup vs baseline: 1.0589x; 1.0589x over previous
#include <cuda_runtime.h>
#include <cstdint>

// ---------------- configuration ----------------
#define S           256         // tile-table stride (num_tile=16 -> nt2=256; supports <=16)
#define MAX_ROWS    8192        // N up to 4.19M at 512 pts/row
#define MAX_CHUNKS  128
#define PPW         512         // points per warp (one hist "row")
#define WPB         8           // warps per block
#define CHUNK       64          // rows per scan chunk
#define GTHREADS    256         // gather block size
#define ITERS       (PPW / 32)  // 16

// ---------------- static scratch (no runtime allocation) ----------------
__device__ int      g_hist [MAX_ROWS * S];    // per-row hist -> exclusive row prefixes
__device__ int      g_chunk[MAX_CHUNKS * S];  // per-chunk totals -> exclusive prefixes
__device__ int      g_offsets[S];             // global tile offsets
__device__ unsigned g_packed[MAX_ROWS * PPW]; // per-point (rank<<16 | key)
__device__ int      g_perm  [MAX_ROWS * PPW]; // perm[r] = source index

// ---------------- helpers ----------------
__device__ __forceinline__ int tile_of(float v, float ts, int nt) {
    int t = (int)floorf(v / ts);
    t = t < 0 ? 0 : t;
    t = t > nt - 1 ? nt - 1 : t;
    return t;
}

// ---------------- pass 1: fused histogram + stable within-row rank ----------------
__global__ void k_hist(const float2* __restrict__ pos, const int* __restrict__ p_nt,
                       int N, int ROWS) {
    __shared__ int sh[WPB * S];   // 8 KB
    const int nt  = *p_nt;
    const int nt2 = nt * nt;
    const float ts = 1024.0f / (float)nt;

    const int w    = threadIdx.x >> 5;
    const int lane = threadIdx.x & 31;
    const int row  = blockIdx.x * WPB + w;

    for (int t = lane; t < nt2; t += 32) sh[w * S + t] = 0;
    __syncwarp();

    if (row >= ROWS) return;

    const int base = row * PPW;
    const unsigned lt_mask = (1u << lane) - 1u;

    // prefetch all position loads (independent of the rank chain)
    int keys[ITERS];
#pragma unroll
    for (int i = 0; i < ITERS; i++) {
        int idx = base + i * 32 + lane;
        if (idx < N) {
            float2 p = __ldg(&pos[idx]);
            int tx = tile_of(p.x, ts, nt);
            int ty = tile_of(p.y, ts, nt);
            keys[i] = ty * nt + tx;
        } else {
            keys[i] = 0x7FFFFFFF;
        }
    }

    // serial stable-rank chain (only dependence: per-warp shared counters)
#pragma unroll
    for (int i = 0; i < ITERS; i++) {
        int idx = base + i * 32 + lane;
        int key = keys[i];
        bool valid = idx < N;

        unsigned m  = __match_any_sync(0xFFFFFFFFu, key);
        int leader  = __ffs(m) - 1;
        int cnt     = __popc(m);
        int rank_lt = __popc(m & lt_mask);

        int old = 0;
        if (lane == leader && valid) {
            old = sh[w * S + key];           // single writer per address
            sh[w * S + key] = old + cnt;
        }
        old = __shfl_sync(0xFFFFFFFFu, old, leader);

        if (valid)
            g_packed[idx] = (unsigned)key | ((unsigned)(old + rank_lt) << 16);
    }
    __syncwarp();
    for (int t = lane; t < nt2; t += 32)
        g_hist[(size_t)row * S + t] = sh[w * S + t];
}

// ---------------- pass 2a: per-tile scan over rows within each chunk ----------------
__global__ void k_scan_rows(const int* __restrict__ p_nt, int ROWS) {
    const int nt  = *p_nt;
    const int nt2 = nt * nt;
    const int c  = blockIdx.x;
    const int r0 = c * CHUNK;
    const int r1 = min(r0 + CHUNK, ROWS);

    for (int t = threadIdx.x; t < nt2; t += blockDim.x) {
        int run = 0;
        for (int r = r0; r < r1; r += 8) {
            int m = min(8, r1 - r);
            int v[8];
#pragma unroll
            for (int j = 0; j < 8; j++)
                if (j < m) v[j] = g_hist[(size_t)(r + j) * S + t];
#pragma unroll
            for (int j = 0; j < 8; j++)
                if (j < m) {
                    g_hist[(size_t)(r + j) * S + t] = run;
                    run += v[j];
                }
        }
        g_chunk[(size_t)c * S + t] = run;
    }
}

// ---------------- pass 2b: scan chunks per tile, then scan over tiles ----------------
__global__ void k_scan_tiles(const int* __restrict__ p_nt, int NCHUNKS,
                             float* __restrict__ out, int N) {
    __shared__ int s[1024];
    const int nt  = *p_nt;
    const int nt2 = nt * nt;
    const int t = threadIdx.x;

    int total = 0;
    if (t < nt2) {
        int run = 0;
        for (int c = 0; c < NCHUNKS; c += 8) {
            int m = min(8, NCHUNKS - c);
            int v[8];
#pragma unroll
            for (int j = 0; j < 8; j++)
                if (j < m) v[j] = g_chunk[(size_t)(c + j) * S + t];
#pragma unroll
            for (int j = 0; j < 8; j++)
                if (j < m) {
                    g_chunk[(size_t)(c + j) * S + t] = run;
                    run += v[j];
                }
        }
        total = run;
    }
    s[t] = total;
    __syncthreads();

    for (int off = 1; off < 1024; off <<= 1) {
        int v = (t >= off) ? s[t - off] : 0;
        __syncthreads();
        s[t] += v;
        __syncthreads();
    }
    int excl = s[t] - total;

    if (t < nt2) {
        g_offsets[t] = excl;
        size_t feat_sz = (size_t)7 * (size_t)N;
        out[feat_sz + t]       = (float)total;  // tile_counts
        out[feat_sz + nt2 + t] = (float)excl;   // tile_offsets
    }
}

// ---------------- pass 3a: permutation scatter, block-cooperative base fuse ----------------
// block b covers points [b*256, b*256+256) -> one row (PPW=512 => row = b/2).
__global__ void k_perm(const int* __restrict__ p_nt, int N) {
    __shared__ int sbase[S];   // fused base row: offsets + chunk + hist
    const int nt2 = (*p_nt) * (*p_nt);

    const int tid = threadIdx.x;
    const int idx0 = blockIdx.x * 256;
    const int row  = idx0 / PPW;
    const int chnk = row / CHUNK;

    if (tid < nt2)
        sbase[tid] = g_offsets[tid]
                   + g_chunk[(size_t)chnk * S + tid]
                   + g_hist[(size_t)row * S + tid];
    __syncthreads();

    int idx = idx0 + tid;
    if (idx < N) {
        unsigned pk = g_packed[idx];
        int key  = (int)(pk & 0xFFFFu);
        int rank = (int)(pk >> 16);
        g_perm[sbase[key] + rank] = idx;
    }
}

// ---------------- pass 3b: gather + compute + coalesced wide stores ----------------
__global__ void k_gather(const float2* __restrict__ pos,
                         const float4* __restrict__ cov,
                         const float*  __restrict__ opac,
                         const int*    __restrict__ p_nt,
                         int N,
                         float* __restrict__ out) {
    __shared__ float s[GTHREADS * 7];   // stride 7 -> conflict-free
    const int nt  = *p_nt;
    const int nt2 = nt * nt;

    const int tid = threadIdx.x;
    const int r0  = blockIdx.x * GTHREADS;
    const int r   = r0 + tid;

    float* __restrict__ out_order = out + (size_t)7 * (size_t)N + 2 * (size_t)nt2;

    if (r < N) {
        int idx = __ldg(&g_perm[r]);
        float2 p  = __ldg(&pos[idx]);
        float4 cv = __ldg(&cov[idx]);
        float  op = __ldg(&opac[idx]);

        float a = cv.x, b = cv.y, c = cv.z, d = cv.w;
        float tr  = a + d;
        float det = a * d - b * c;
        float t1  = 0.5f * tr;
        float t2  = 0.5f * sqrtf(fmaxf(tr * tr - 4.0f * det, 0.0f));
        float rad = fmaxf(t1 - t2, t1 + t2);
        float inv_det = 1.0f / det;

        float* sf = s + tid * 7;
        sf[0] = p.x;  sf[1] = p.y;
        sf[2] =  d * inv_det;
        sf[3] = -b * inv_det;
        sf[4] =  a * inv_det;
        sf[5] = op;   sf[6] = rad;

        out_order[r] = (float)idx;
    }
    __syncthreads();

    int count = min(GTHREADS, N - r0);
    if (count == GTHREADS) {
        // full tile: 1792 floats = 448 float4, base aligned (r0 multiple of 256)
        float4* dst = (float4*)(out + (size_t)r0 * 7);
        const float4* src = (const float4*)s;
#pragma unroll
        for (int i = 0; i < 2; i++) {
            int j = tid + i * GTHREADS;
            if (j < (GTHREADS * 7) / 4) dst[j] = src[j];
        }
    } else if (count > 0) {
        float* dst = out + (size_t)r0 * 7;
        int nf = count * 7;
        for (int j = tid; j < nf; j += GTHREADS) dst[j] = s[j];
    }
}

// ---------------- launch ----------------
extern "C" void kernel_launch(void* const* d_in, const int* in_sizes, int n_in,
                              void* d_out, int out_size) {
    const float2* pos  = (const float2*)d_in[0];
    const float4* cov  = (const float4*)d_in[1];
    const float*  opac = (const float*) d_in[2];
    const int*    p_nt = (const int*)   d_in[3];
    float* out = (float*)d_out;

    const int N       = in_sizes[0] / 2;
    const int ROWS    = (N + PPW - 1) / PPW;
    const int NBLOCKS = (ROWS + WPB - 1) / WPB;
    const int NCHUNKS = (ROWS + CHUNK - 1) / CHUNK;
    const int GBLOCKS = (N + GTHREADS - 1) / GTHREADS;
    const int PBLOCKS = (N + 255) / 256;

    k_hist      <<<NBLOCKS, 256>>>(pos, p_nt, N, ROWS);
    k_scan_rows <<<NCHUNKS, 256>>>(p_nt, ROWS);
    k_scan_tiles<<<1, 1024>>>(p_nt, NCHUNKS, out, N);
    k_perm      <<<PBLOCKS, 256>>>(p_nt, N);
    k_gather    <<<GBLOCKS, GTHREADS>>>(pos, cov, opac, p_nt, N, out);
}

// round 11
// speedup vs baseline: 1.0618x; 1.0028x over previous
#include <cuda_runtime.h>
#include <cstdint>

// ---------------- configuration ----------------
#define S           256         // tile table width (num_tile<=16 -> nt2<=256)
#define RP          1024        // rows pad (column-major stride); N up to 4.19M
#define PPB         4096        // points per block (one hist "row")
#define WPB         8           // warps per block
#define PPW         512         // points per warp within block (contiguous!)
#define ITERS       (PPW / 32)  // 16
#define GTHREADS    256

// ---------------- static scratch (no runtime allocation) ----------------
__device__ int      g_hist[S * RP];        // column-major: [tile][row] counts -> excl prefixes
__device__ int      g_tot [S];             // per-tile totals
__device__ int      g_offsets[S];          // global tile offsets
__device__ unsigned g_packed[RP * PPB];    // per-point (block_rank<<16 | key)
__device__ int      g_perm  [RP * PPB];    // perm[r] = source index

// ---------------- helpers ----------------
__device__ __forceinline__ int tile_of(float v, float ts, int nt) {
    int t = (int)floorf(v / ts);
    t = t < 0 ? 0 : t;
    t = t > nt - 1 ? nt - 1 : t;
    return t;
}

// ---------------- pass 1: block histogram + stable block-level rank ----------------
__global__ void k_hist(const float2* __restrict__ pos, const int* __restrict__ p_nt,
                       int N) {
    __shared__ int sh[WPB * S];   // 8 KB
    const int nt  = *p_nt;
    const int nt2 = nt * nt;
    const float ts = 1024.0f / (float)nt;

    const int tid  = threadIdx.x;
    const int w    = tid >> 5;
    const int lane = tid & 31;
    const int row  = blockIdx.x;

    for (int t = tid; t < WPB * S; t += 256) sh[t] = 0;
    __syncthreads();

    // warp w owns contiguous points [row*PPB + w*PPW, +PPW) -> warp order == index order
    const int base = row * PPB + w * PPW;
    const unsigned lt_mask = (1u << lane) - 1u;

    // prefetch keys (independent of the rank chain)
    int keys[ITERS];
#pragma unroll
    for (int i = 0; i < ITERS; i++) {
        int idx = base + i * 32 + lane;
        if (idx < N) {
            float2 p = __ldg(&pos[idx]);
            keys[i] = tile_of(p.y, ts, nt) * nt + tile_of(p.x, ts, nt);
        } else {
            keys[i] = -1;
        }
    }

    // serial stable-rank chain on per-warp counters
    int ranks[ITERS];
#pragma unroll
    for (int i = 0; i < ITERS; i++) {
        int key = keys[i];
        bool valid = key >= 0;

        unsigned m  = __match_any_sync(0xFFFFFFFFu, key);
        int leader  = __ffs(m) - 1;
        int cnt     = __popc(m);
        int rank_lt = __popc(m & lt_mask);

        int old = 0;
        if (lane == leader && valid) {
            old = sh[w * S + key];           // single writer per address
            sh[w * S + key] = old + cnt;
        }
        old = __shfl_sync(0xFFFFFFFFu, old, leader);
        ranks[i] = old + rank_lt;
    }
    __syncthreads();

    // block combine: warp-exclusive prefix per tile + block total (column-major store)
    if (tid < nt2) {
        int run = 0;
#pragma unroll
        for (int w2 = 0; w2 < WPB; w2++) {
            int v = sh[w2 * S + tid];
            sh[w2 * S + tid] = run;
            run += v;
        }
        g_hist[(size_t)tid * RP + row] = run;
    }
    __syncthreads();

    // emit packed (key | block_rank<<16); block_rank < 4096 fits u16
#pragma unroll
    for (int i = 0; i < ITERS; i++) {
        int idx = base + i * 32 + lane;
        if (keys[i] >= 0) {
            int r = sh[w * S + keys[i]] + ranks[i];
            g_packed[idx] = (unsigned)keys[i] | ((unsigned)r << 16);
        }
    }
}

// ---------------- pass 2a: per-tile scan over rows (contiguous, one block/tile) ----------------
__global__ void k_scan(const int* __restrict__ p_nt, int ROWS) {
    __shared__ int s[1024];
    const int nt2 = (*p_nt) * (*p_nt);
    const int t = blockIdx.x;
    if (t >= nt2) return;

    const int r = threadIdx.x;
    int v = (r < ROWS) ? g_hist[(size_t)t * RP + r] : 0;
    s[r] = v;
    __syncthreads();

    for (int off = 1; off < 1024; off <<= 1) {
        int x = (r >= off) ? s[r - off] : 0;
        __syncthreads();
        s[r] += x;
        __syncthreads();
    }

    if (r < ROWS) g_hist[(size_t)t * RP + r] = s[r] - v;   // exclusive prefix
    if (r == 1023) g_tot[t] = s[1023];
}

// ---------------- pass 2b: scan tile totals -> offsets, emit counts/offsets ----------------
__global__ void k_offsets(const int* __restrict__ p_nt, float* __restrict__ out, int N) {
    __shared__ int s[256];
    const int nt2 = (*p_nt) * (*p_nt);
    const int t = threadIdx.x;

    int v = (t < nt2) ? g_tot[t] : 0;
    s[t] = v;
    __syncthreads();

    for (int off = 1; off < 256; off <<= 1) {
        int x = (t >= off) ? s[t - off] : 0;
        __syncthreads();
        s[t] += x;
        __syncthreads();
    }
    int excl = s[t] - v;

    if (t < nt2) {
        g_offsets[t] = excl;
        size_t feat_sz = (size_t)7 * (size_t)N;
        out[feat_sz + t]       = (float)v;     // tile_counts
        out[feat_sz + nt2 + t] = (float)excl;  // tile_offsets
    }
}

// ---------------- pass 3a: permutation scatter (no shared, no sync) ----------------
__global__ void k_perm(int N) {
    int idx = blockIdx.x * 256 + threadIdx.x;
    if (idx >= N) return;
    unsigned pk = g_packed[idx];
    int key  = (int)(pk & 0xFFFFu);
    int rank = (int)(pk >> 16);
    int row  = idx / PPB;
    int dst  = g_offsets[key] + g_hist[(size_t)key * RP + row] + rank;
    g_perm[dst] = idx;
}

// ---------------- pass 3b: gather + compute + coalesced wide stores ----------------
__global__ void k_gather(const float2* __restrict__ pos,
                         const float4* __restrict__ cov,
                         const float*  __restrict__ opac,
                         const int*    __restrict__ p_nt,
                         int N,
                         float* __restrict__ out) {
    __shared__ float s[GTHREADS * 7];   // stride 7 -> conflict-free
    const int nt  = *p_nt;
    const int nt2 = nt * nt;

    const int tid = threadIdx.x;
    const int r0  = blockIdx.x * GTHREADS;
    const int r   = r0 + tid;

    float* __restrict__ out_order = out + (size_t)7 * (size_t)N + 2 * (size_t)nt2;

    if (r < N) {
        int idx = __ldg(&g_perm[r]);
        float2 p  = __ldg(&pos[idx]);
        float4 cv = __ldg(&cov[idx]);
        float  op = __ldg(&opac[idx]);

        float a = cv.x, b = cv.y, c = cv.z, d = cv.w;
        float tr  = a + d;
        float det = a * d - b * c;
        float t1  = 0.5f * tr;
        float t2  = 0.5f * sqrtf(fmaxf(tr * tr - 4.0f * det, 0.0f));
        float rad = fmaxf(t1 - t2, t1 + t2);
        float inv_det = 1.0f / det;

        float* sf = s + tid * 7;
        sf[0] = p.x;  sf[1] = p.y;
        sf[2] =  d * inv_det;
        sf[3] = -b * inv_det;
        sf[4] =  a * inv_det;
        sf[5] = op;   sf[6] = rad;

        out_order[r] = (float)idx;
    }
    __syncthreads();

    int count = min(GTHREADS, N - r0);
    if (count == GTHREADS) {
        // full tile: 1792 floats = 448 float4, base aligned (r0 multiple of 256)
        float4* dst = (float4*)(out + (size_t)r0 * 7);
        const float4* src = (const float4*)s;
#pragma unroll
        for (int i = 0; i < 2; i++) {
            int j = tid + i * GTHREADS;
            if (j < (GTHREADS * 7) / 4) dst[j] = src[j];
        }
    } else if (count > 0) {
        float* dst = out + (size_t)r0 * 7;
        int nf = count * 7;
        for (int j = tid; j < nf; j += GTHREADS) dst[j] = s[j];
    }
}

// ---------------- launch ----------------
extern "C" void kernel_launch(void* const* d_in, const int* in_sizes, int n_in,
                              void* d_out, int out_size) {
    const float2* pos  = (const float2*)d_in[0];
    const float4* cov  = (const float4*)d_in[1];
    const float*  opac = (const float*) d_in[2];
    const int*    p_nt = (const int*)   d_in[3];
    float* out = (float*)d_out;

    const int N       = in_sizes[0] / 2;
    const int ROWS    = (N + PPB - 1) / PPB;
    const int GBLOCKS = (N + GTHREADS - 1) / GTHREADS;
    const int PBLOCKS = (N + 255) / 256;

    k_hist   <<<ROWS, 256>>>(pos, p_nt, N);
    k_scan   <<<S, 1024>>>(p_nt, ROWS);
    k_offsets<<<1, 256>>>(p_nt, out, N);
    k_perm   <<<PBLOCKS, 256>>>(N);
    k_gather <<<GBLOCKS, GTHREADS>>>(pos, cov, opac, p_nt, N, out);
}

// round 12
// speedup vs baseline: 1.2237x; 1.1525x over previous
#include <cuda_runtime.h>
#include <cstdint>

// ---------------- configuration ----------------
#define S           256         // tile table width (num_tile<=16 -> nt2<=256)
#define RP          1024        // rows pad (column-major stride); N up to 4.19M
#define PPB         4096        // points per block
#define WPB         16          // warps per block (512 threads)
#define PPW         256         // contiguous points per warp
#define ITERS       (PPW / 32)  // 8
#define HTHREADS    512
#define GTHREADS    256

// ---------------- static scratch (no runtime allocation) ----------------
__device__ int      g_hist [S * RP];        // column-major [tile][row] counts -> excl prefixes
__device__ int      g_lbase[RP * S];        // per-block tile-local exclusive base
__device__ int      g_tot  [S];             // per-tile totals
__device__ int      g_offsets[S];           // global tile offsets
__device__ unsigned g_packed[RP * PPB];     // per-point (local_dst<<16 | key)
__device__ int      g_perm  [RP * PPB];     // perm[r] = source index
__device__ float4   g_feat  [2 * RP * PPB]; // 32B AoS feat record per point

// ---------------- helpers ----------------
__device__ __forceinline__ int tile_of(float v, float ts, int nt) {
    int t = (int)floorf(v / ts);
    t = t < 0 ? 0 : t;
    t = t > nt - 1 ? nt - 1 : t;
    return t;
}

// ---- pass 1: feat compute + block histogram + stable block-local sorted position ----
__global__ void k_hist(const float2* __restrict__ pos,
                       const float4* __restrict__ cov,
                       const float*  __restrict__ opac,
                       const int* __restrict__ p_nt, int N) {
    __shared__ int sh[WPB * S];   // 16 KB per-warp counters -> warp bases
    __shared__ int s2[S];         // tile totals -> inclusive scan
    __shared__ int sL[S];         // tile-local exclusive base
    const int nt  = *p_nt;
    const int nt2 = nt * nt;
    const float ts = 1024.0f / (float)nt;

    const int tid  = threadIdx.x;
    const int w    = tid >> 5;
    const int lane = tid & 31;
    const int row  = blockIdx.x;

    for (int t = tid; t < WPB * S; t += HTHREADS) sh[t] = 0;
    __syncthreads();

    const int base = row * PPB + w * PPW;   // warp owns contiguous span
    const unsigned lt_mask = (1u << lane) - 1u;

    // load, compute feat (written here: coalesced), derive keys
    int keys[ITERS];
#pragma unroll
    for (int i = 0; i < ITERS; i++) {
        int idx = base + i * 32 + lane;
        if (idx < N) {
            float2 p  = __ldg(&pos[idx]);
            float4 cv = __ldg(&cov[idx]);
            float  op = __ldg(&opac[idx]);

            float a = cv.x, b = cv.y, c = cv.z, d = cv.w;
            float tr  = a + d;
            float det = a * d - b * c;
            float t1  = 0.5f * tr;
            float t2  = 0.5f * sqrtf(fmaxf(tr * tr - 4.0f * det, 0.0f));
            float rad = fmaxf(t1 - t2, t1 + t2);
            float inv_det = 1.0f / det;

            g_feat[2 * (size_t)idx]     = make_float4(p.x, p.y, d * inv_det, -b * inv_det);
            g_feat[2 * (size_t)idx + 1] = make_float4(a * inv_det, op, rad, 0.0f);

            keys[i] = tile_of(p.y, ts, nt) * nt + tile_of(p.x, ts, nt);
        } else {
            keys[i] = -1;
        }
    }

    // serial stable-rank chain on per-warp counters
    int ranks[ITERS];
#pragma unroll
    for (int i = 0; i < ITERS; i++) {
        int key = keys[i];
        bool valid = key >= 0;

        unsigned m  = __match_any_sync(0xFFFFFFFFu, key);
        int leader  = __ffs(m) - 1;
        int cnt     = __popc(m);
        int rank_lt = __popc(m & lt_mask);

        int old = 0;
        if (lane == leader && valid) {
            old = sh[w * S + key];            // single writer per address
            sh[w * S + key] = old + cnt;
        }
        old = __shfl_sync(0xFFFFFFFFu, old, leader);
        ranks[i] = old + rank_lt;
    }
    __syncthreads();

    // combine: warp-exclusive prefix per tile; block totals to g_hist (column-major)
    int tot = 0;
    if (tid < S) {
        int run = 0;
#pragma unroll
        for (int w2 = 0; w2 < WPB; w2++) {
            int v = sh[w2 * S + tid];
            sh[w2 * S + tid] = run;
            run += v;
        }
        tot = run;
        s2[tid] = run;
        if (tid < nt2) g_hist[(size_t)tid * RP + row] = run;
    }
    __syncthreads();

    // exclusive scan over tiles -> block-local sorted base per tile
    for (int off = 1; off < S; off <<= 1) {
        int v = (tid < S && tid >= off) ? s2[tid - off] : 0;
        __syncthreads();
        if (tid < S) s2[tid] += v;
        __syncthreads();
    }
    if (tid < S) {
        sL[tid] = s2[tid] - tot;
        if (tid < nt2) g_lbase[(size_t)row * S + tid] = sL[tid];
    }
    __syncthreads();

    // emit packed: key | block-sorted local position << 16  (local_dst < 4096)
#pragma unroll
    for (int i = 0; i < ITERS; i++) {
        int key = keys[i];
        if (key >= 0) {
            int idx = base + i * 32 + lane;
            int ld  = sL[key] + sh[w * S + key] + ranks[i];
            g_packed[idx] = (unsigned)key | ((unsigned)ld << 16);
        }
    }
}

// ---- pass 2a: per-tile scan over rows (contiguous column, one block/tile) ----
__global__ void k_scan(const int* __restrict__ p_nt, int ROWS) {
    __shared__ int s[1024];
    const int nt2 = (*p_nt) * (*p_nt);
    const int t = blockIdx.x;
    if (t >= nt2) return;

    const int r = threadIdx.x;
    int v = (r < ROWS) ? g_hist[(size_t)t * RP + r] : 0;
    s[r] = v;
    __syncthreads();

    for (int off = 1; off < 1024; off <<= 1) {
        int x = (r >= off) ? s[r - off] : 0;
        __syncthreads();
        s[r] += x;
        __syncthreads();
    }

    if (r < ROWS) g_hist[(size_t)t * RP + r] = s[r] - v;   // exclusive prefix
    if (r == 1023) g_tot[t] = s[1023];
}

// ---- pass 2b: scan tile totals -> global offsets; emit counts/offsets ----
__global__ void k_offsets(const int* __restrict__ p_nt, float* __restrict__ out, int N) {
    __shared__ int s[256];
    const int nt2 = (*p_nt) * (*p_nt);
    const int t = threadIdx.x;

    int v = (t < nt2) ? g_tot[t] : 0;
    s[t] = v;
    __syncthreads();

    for (int off = 1; off < 256; off <<= 1) {
        int x = (t >= off) ? s[t - off] : 0;
        __syncthreads();
        s[t] += x;
        __syncthreads();
    }
    int excl = s[t] - v;

    if (t < nt2) {
        g_offsets[t] = excl;
        size_t feat_sz = (size_t)7 * (size_t)N;
        out[feat_sz + t]       = (float)v;     // tile_counts
        out[feat_sz + nt2 + t] = (float)excl;  // tile_offsets
    }
}

// ---- pass 3a: permutation via SMEM staging -> run-coalesced global writes ----
__global__ void k_perm(const int* __restrict__ p_nt, int N) {
    __shared__ int      D[S];          // global base - local base, per tile
    __shared__ unsigned stage[PPB];    // 16 KB: block-sorted (key<<16 | local idx)
    const int nt2 = (*p_nt) * (*p_nt);

    const int tid = threadIdx.x;
    const int row = blockIdx.x;
    const int base = row * PPB;
    const int nv = min(PPB, N - base);

    if (tid < nt2)
        D[tid] = g_offsets[tid]
               + g_hist[(size_t)tid * RP + row]
               - g_lbase[(size_t)row * S + tid];
    __syncthreads();

    // scatter into SMEM at block-sorted position (random SMEM = cheap)
#pragma unroll
    for (int i = 0; i < PPB / HTHREADS; i++) {
        int j = tid + i * HTHREADS;
        if (j < nv) {
            unsigned pk = g_packed[base + j];           // coalesced
            stage[pk >> 16] = ((pk & 0xFFFFu) << 16) | (unsigned)j;
        }
    }
    __syncthreads();

    // sorted-order writeout: consecutive j -> same-tile runs -> few sectors/warp
#pragma unroll
    for (int i = 0; i < PPB / HTHREADS; i++) {
        int j = tid + i * HTHREADS;
        if (j < nv) {
            unsigned v = stage[j];
            g_perm[j + D[v >> 16]] = base + (int)(v & 0xFFFFu);
        }
    }
}

// ---- pass 3b: single-sector gather of 32B feat records + coalesced stores ----
__global__ void k_gather(const int* __restrict__ p_nt, int N, float* __restrict__ out) {
    __shared__ float s[GTHREADS * 7];   // stride 7 -> conflict-free
    const int nt2 = (*p_nt) * (*p_nt);

    const int tid = threadIdx.x;
    const int r0  = blockIdx.x * GTHREADS;
    const int r   = r0 + tid;

    float* __restrict__ out_order = out + (size_t)7 * (size_t)N + 2 * (size_t)nt2;

    if (r < N) {
        int idx = __ldg(&g_perm[r]);
        float4 f0 = __ldg(&g_feat[2 * (size_t)idx]);       // same 32B sector
        float4 f1 = __ldg(&g_feat[2 * (size_t)idx + 1]);

        float* sf = s + tid * 7;
        sf[0] = f0.x; sf[1] = f0.y; sf[2] = f0.z; sf[3] = f0.w;
        sf[4] = f1.x; sf[5] = f1.y; sf[6] = f1.z;

        out_order[r] = (float)idx;
    }
    __syncthreads();

    int count = min(GTHREADS, N - r0);
    if (count == GTHREADS) {
        // full tile: 1792 floats = 448 float4, base aligned (r0 multiple of 256)
        float4* dst = (float4*)(out + (size_t)r0 * 7);
        const float4* src = (const float4*)s;
#pragma unroll
        for (int i = 0; i < 2; i++) {
            int j = tid + i * GTHREADS;
            if (j < (GTHREADS * 7) / 4) dst[j] = src[j];
        }
    } else if (count > 0) {
        float* dst = out + (size_t)r0 * 7;
        int nf = count * 7;
        for (int j = tid; j < nf; j += GTHREADS) dst[j] = s[j];
    }
}

// ---------------- launch ----------------
extern "C" void kernel_launch(void* const* d_in, const int* in_sizes, int n_in,
                              void* d_out, int out_size) {
    const float2* pos  = (const float2*)d_in[0];
    const float4* cov  = (const float4*)d_in[1];
    const float*  opac = (const float*) d_in[2];
    const int*    p_nt = (const int*)   d_in[3];
    float* out = (float*)d_out;

    const int N       = in_sizes[0] / 2;
    const int ROWS    = (N + PPB - 1) / PPB;
    const int GBLOCKS = (N + GTHREADS - 1) / GTHREADS;

    k_hist   <<<ROWS, HTHREADS>>>(pos, cov, opac, p_nt, N);
    k_scan   <<<S, 1024>>>(p_nt, ROWS);
    k_offsets<<<1, 256>>>(p_nt, out, N);
    k_perm   <<<ROWS, HTHREADS>>>(p_nt, N);
    k_gather <<<GBLOCKS, GTHREADS>>>(p_nt, N, out);
}